// round 2
// baseline (speedup 1.0000x reference)
#include <cuda_runtime.h>
#include <cuda_bf16.h>
#include <cstdint>

// ---------------------------------------------------------------------------
// Problem constants: B=16, S=2048, D=128
// ---------------------------------------------------------------------------
#define B_  16
#define S_  2048
#define D_  128
#define BM  128          // q rows per CTA
#define BN  64           // kv cols per tile
#define NT  (S_ / BN)    // 32 tiles
#define SCP 68           // scale tile row stride (floats), 16B-aligned, conflict-spread

// SMEM layout (bytes). bf16 tiles use SW128 blocked-atom layout.
#define SM_QHI 0
#define SM_QLO 32768
#define SM_KHI 65536
#define SM_KLO 81920
#define SM_VHI 98304
#define SM_VLO 114688
#define SM_SC  131072
#define SM_TOTAL (SM_SC + BM * SCP * 4)   // 165888 B

// ---------------------------------------------------------------------------
// Helpers (ALL plain sm_80-level PTX: compiles for base sm_103 target)
// ---------------------------------------------------------------------------
__device__ __forceinline__ uint32_t smem_u32(const void* p) {
    uint32_t a;
    asm("{ .reg .u64 t; cvta.to.shared.u64 t, %1; cvt.u32.u64 %0, t; }" : "=r"(a) : "l"(p));
    return a;
}
__device__ __forceinline__ uint32_t sw128(uint32_t o) { return o ^ ((o >> 3) & 0x70); }

// SW128 blocked-atom K-major byte offset: atom = 8 rows x 64 bf16 (1024 B),
// atom grid (rows/8) x (cols/64), atom index = (row>>3) + (col>>6)*rdiv8.
__device__ __forceinline__ uint32_t koff(int row, int col, int rdiv8) {
    uint32_t o = ((uint32_t)((row >> 3) + (col >> 6) * rdiv8) << 10)
               | ((uint32_t)(row & 7) << 7) | ((uint32_t)(col & 63) << 1);
    return sw128(o);
}

__device__ __forceinline__ void split2(float a, float b, uint32_t& hi, uint32_t& lo) {
    __nv_bfloat16 ha = __float2bfloat16(a);
    __nv_bfloat16 hb = __float2bfloat16(b);
    __nv_bfloat16 la = __float2bfloat16(a - __bfloat162float(ha));
    __nv_bfloat16 lb = __float2bfloat16(b - __bfloat162float(hb));
    hi = ((uint32_t)__bfloat16_as_ushort(hb) << 16) | (uint32_t)__bfloat16_as_ushort(ha);
    lo = ((uint32_t)__bfloat16_as_ushort(lb) << 16) | (uint32_t)__bfloat16_as_ushort(la);
}

__device__ __forceinline__ float ex2f(float x) {
    float y; asm("ex2.approx.ftz.f32 %0, %1;" : "=f"(y) : "f"(x)); return y;
}

#define LDSM4(R0, R1, R2, R3, ADDR) \
    asm volatile("ldmatrix.sync.aligned.m8n8.x4.shared.b16 {%0,%1,%2,%3}, [%4];" \
        : "=r"(R0), "=r"(R1), "=r"(R2), "=r"(R3) : "r"(ADDR))

#define LDSM4T(R0, R1, R2, R3, ADDR) \
    asm volatile("ldmatrix.sync.aligned.m8n8.x4.trans.shared.b16 {%0,%1,%2,%3}, [%4];" \
        : "=r"(R0), "=r"(R1), "=r"(R2), "=r"(R3) : "r"(ADDR))

#define MMA16816(D, A0, A1, A2, A3, B0, B1) \
    asm volatile("mma.sync.aligned.m16n8k16.row.col.f32.bf16.bf16.f32 " \
        "{%0,%1,%2,%3}, {%4,%5,%6,%7}, {%8,%9}, {%0,%1,%2,%3};" \
        : "+f"((D)[0]), "+f"((D)[1]), "+f"((D)[2]), "+f"((D)[3]) \
        : "r"(A0), "r"(A1), "r"(A2), "r"(A3), "r"(B0), "r"(B1))

// ---------------------------------------------------------------------------
// Flash attention: 1 CTA = (batch, 128 q rows), 8 warps x 16 rows each.
// bf16 hi/lo 3-term emulated-fp32 for both QK^T and PV.
// ---------------------------------------------------------------------------
__global__ void __launch_bounds__(256, 1)
attn_kernel(const float* __restrict__ Q, const float* __restrict__ K,
            const float* __restrict__ V, const float* __restrict__ SC,
            float* __restrict__ Out)
{
    extern __shared__ char smem[];
    const uint32_t sb = smem_u32(smem);
    const int tid = threadIdx.x;
    const int wid = tid >> 5;
    const int lid = tid & 31;
    const int gr  = lid >> 2;     // group row within m16n8 fragment
    const int t4  = lid & 3;
    const int mr  = wid * 16;     // this warp's q-row base within the CTA tile
    const int q0  = blockIdx.x * BM;
    const int b   = blockIdx.y;
    const float L2E = 1.4426950408889634f;

    const float* Qb = Q + ((size_t)b * S_ + q0) * D_;
    const float* Kb = K + (size_t)b * S_ * D_;
    const float* Vb = V + (size_t)b * S_ * D_;
    float* ssc = (float*)(smem + SM_SC);

    // ---- Q tile (hi/lo bf16), loaded once per CTA ----
    #pragma unroll
    for (int it = 0; it < 16; ++it) {
        int i = tid + it * 256;
        int row = i >> 5, c4 = i & 31;
        float4 v = *(const float4*)(Qb + row * D_ + c4 * 4);
        uint32_t h0, h1, l0, l1;
        split2(v.x, v.y, h0, l0); split2(v.z, v.w, h1, l1);
        uint32_t off = koff(row, c4 * 4, 16);
        *(uint2*)(smem + SM_QHI + off) = make_uint2(h0, h1);
        *(uint2*)(smem + SM_QLO + off) = make_uint2(l0, l1);
    }

    // O accumulator: 16 rows x 128 cols per warp -> 16 nblocks x 4 floats
    float o[16][4];
    #pragma unroll
    for (int nd = 0; nd < 16; ++nd) { o[nd][0] = o[nd][1] = o[nd][2] = o[nd][3] = 0.f; }
    float m0 = -INFINITY, m1 = -INFINITY, l0s = 0.f, l1s = 0.f;

    // ldmatrix lane constants
    const int rowq  = mr + (lid & 7) + ((lid >> 3) & 1) * 8; // Q A-frag row
    const int rk_b  = ((lid >> 4) << 3) + (lid & 7);         // K B-frag row base
    const int rv_b  = (((lid >> 3) & 1) << 3) + (lid & 7);   // V B-frag (trans) row base
    const int colql = (lid >> 4) * 8;                        // Q A-frag col lane term
    const int colkl = ((lid >> 3) & 1) * 8;                  // K B-frag col lane term

    for (int t = 0; t < NT; ++t) {
        const int kv0 = t * BN;

        // ---- K tile hi/lo ----
        #pragma unroll
        for (int it = 0; it < 8; ++it) {
            int i = tid + it * 256;
            int row = i >> 5, c4 = i & 31;
            float4 v = *(const float4*)(Kb + (size_t)(kv0 + row) * D_ + c4 * 4);
            uint32_t h0, h1, lo0, lo1;
            split2(v.x, v.y, h0, lo0); split2(v.z, v.w, h1, lo1);
            uint32_t off = koff(row, c4 * 4, 8);
            *(uint2*)(smem + SM_KHI + off) = make_uint2(h0, h1);
            *(uint2*)(smem + SM_KLO + off) = make_uint2(lo0, lo1);
        }
        // ---- V tile hi/lo (kv-major, same as loaded) ----
        #pragma unroll
        for (int it = 0; it < 8; ++it) {
            int i = tid + it * 256;
            int row = i >> 5, c4 = i & 31;
            float4 v = *(const float4*)(Vb + (size_t)(kv0 + row) * D_ + c4 * 4);
            uint32_t h0, h1, lo0, lo1;
            split2(v.x, v.y, h0, lo0); split2(v.z, v.w, h1, lo1);
            uint32_t off = koff(row, c4 * 4, 8);
            *(uint2*)(smem + SM_VHI + off) = make_uint2(h0, h1);
            *(uint2*)(smem + SM_VLO + off) = make_uint2(lo0, lo1);
        }
        // ---- scale tile, premultiplied by log2(e) ----
        #pragma unroll
        for (int it = 0; it < 8; ++it) {
            int i = tid + it * 256;
            int row = i >> 4, c4 = i & 15;
            float4 v = *(const float4*)(SC + (size_t)(q0 + row) * S_ + kv0 + c4 * 4);
            float* d = ssc + row * SCP + c4 * 4;
            d[0] = v.x * L2E; d[1] = v.y * L2E; d[2] = v.z * L2E; d[3] = v.w * L2E;
        }
        __syncthreads();

        // ---- QK^T: S = Qhi*Khi + Qhi*Klo + Qlo*Khi ----
        float c[8][4];
        #pragma unroll
        for (int nb = 0; nb < 8; ++nb) { c[nb][0] = c[nb][1] = c[nb][2] = c[nb][3] = 0.f; }
        #pragma unroll
        for (int ks = 0; ks < 8; ++ks) {
            const int cb = ks * 16;
            uint32_t qoff = koff(rowq, cb + colql, 16);
            uint32_t ah0, ah1, ah2, ah3, al0, al1, al2, al3;
            LDSM4(ah0, ah1, ah2, ah3, sb + SM_QHI + qoff);
            LDSM4(al0, al1, al2, al3, sb + SM_QLO + qoff);
            #pragma unroll
            for (int np = 0; np < 4; ++np) {
                uint32_t kof = koff(np * 16 + rk_b, cb + colkl, 8);
                uint32_t bh0, bh1, bh2, bh3, bl0, bl1, bl2, bl3;
                LDSM4(bh0, bh1, bh2, bh3, sb + SM_KHI + kof);
                LDSM4(bl0, bl1, bl2, bl3, sb + SM_KLO + kof);
                MMA16816(c[2*np],   ah0, ah1, ah2, ah3, bh0, bh1);
                MMA16816(c[2*np],   ah0, ah1, ah2, ah3, bl0, bl1);
                MMA16816(c[2*np],   al0, al1, al2, al3, bh0, bh1);
                MMA16816(c[2*np+1], ah0, ah1, ah2, ah3, bh2, bh3);
                MMA16816(c[2*np+1], ah0, ah1, ah2, ah3, bl2, bl3);
                MMA16816(c[2*np+1], al0, al1, al2, al3, bh2, bh3);
            }
        }

        // ---- online softmax (all in registers) ----
        const int r0 = mr + gr, r1 = r0 + 8;
        float mt0 = -INFINITY, mt1 = -INFINITY;
        #pragma unroll
        for (int nb = 0; nb < 8; ++nb) {
            float2 s0 = *(const float2*)(ssc + r0 * SCP + nb * 8 + t4 * 2);
            float2 s1 = *(const float2*)(ssc + r1 * SCP + nb * 8 + t4 * 2);
            c[nb][0] *= s0.x; c[nb][1] *= s0.y;
            c[nb][2] *= s1.x; c[nb][3] *= s1.y;
            mt0 = fmaxf(mt0, fmaxf(c[nb][0], c[nb][1]));
            mt1 = fmaxf(mt1, fmaxf(c[nb][2], c[nb][3]));
        }
        mt0 = fmaxf(mt0, __shfl_xor_sync(0xffffffffu, mt0, 1));
        mt0 = fmaxf(mt0, __shfl_xor_sync(0xffffffffu, mt0, 2));
        mt1 = fmaxf(mt1, __shfl_xor_sync(0xffffffffu, mt1, 1));
        mt1 = fmaxf(mt1, __shfl_xor_sync(0xffffffffu, mt1, 2));
        const float m0n = fmaxf(m0, mt0), m1n = fmaxf(m1, mt1);
        const float a0 = ex2f(m0 - m0n), a1 = ex2f(m1 - m1n);
        #pragma unroll
        for (int nd = 0; nd < 16; ++nd) {
            o[nd][0] *= a0; o[nd][1] *= a0; o[nd][2] *= a1; o[nd][3] *= a1;
        }
        float ls0 = 0.f, ls1 = 0.f;
        uint32_t phi[8][2], plo[8][2];
        #pragma unroll
        for (int nb = 0; nb < 8; ++nb) {
            float p00 = ex2f(c[nb][0] - m0n), p01 = ex2f(c[nb][1] - m0n);
            float p10 = ex2f(c[nb][2] - m1n), p11 = ex2f(c[nb][3] - m1n);
            ls0 += p00 + p01; ls1 += p10 + p11;
            split2(p00, p01, phi[nb][0], plo[nb][0]);
            split2(p10, p11, phi[nb][1], plo[nb][1]);
        }
        ls0 += __shfl_xor_sync(0xffffffffu, ls0, 1);
        ls0 += __shfl_xor_sync(0xffffffffu, ls0, 2);
        ls1 += __shfl_xor_sync(0xffffffffu, ls1, 1);
        ls1 += __shfl_xor_sync(0xffffffffu, ls1, 2);
        l0s = l0s * a0 + ls0; l1s = l1s * a1 + ls1;
        m0 = m0n; m1 = m1n;

        // ---- PV: O += Phi*Vhi + Phi*Vlo + Plo*Vhi ----
        // P A-frags come directly from the softmax'd accumulator layout.
        #pragma unroll
        for (int kk = 0; kk < 4; ++kk) {
            uint32_t pah0 = phi[2*kk][0],   pah1 = phi[2*kk][1];
            uint32_t pah2 = phi[2*kk+1][0], pah3 = phi[2*kk+1][1];
            uint32_t pal0 = plo[2*kk][0],   pal1 = plo[2*kk][1];
            uint32_t pal2 = plo[2*kk+1][0], pal3 = plo[2*kk+1][1];
            const int rv = kk * 16 + rv_b;
            #pragma unroll
            for (int np = 0; np < 8; ++np) {
                int cv = (2 * np + (lid >> 4)) * 8;
                uint32_t voff = koff(rv, cv, 8);
                uint32_t vh0, vh1, vh2, vh3, vl0, vl1, vl2, vl3;
                LDSM4T(vh0, vh1, vh2, vh3, sb + SM_VHI + voff);
                LDSM4T(vl0, vl1, vl2, vl3, sb + SM_VLO + voff);
                MMA16816(o[2*np],   pah0, pah1, pah2, pah3, vh0, vh1);
                MMA16816(o[2*np],   pah0, pah1, pah2, pah3, vl0, vl1);
                MMA16816(o[2*np],   pal0, pal1, pal2, pal3, vh0, vh1);
                MMA16816(o[2*np+1], pah0, pah1, pah2, pah3, vh2, vh3);
                MMA16816(o[2*np+1], pah0, pah1, pah2, pah3, vl2, vl3);
                MMA16816(o[2*np+1], pal0, pal1, pal2, pal3, vh2, vh3);
            }
        }
        __syncthreads();   // protect K/V/SC smem reuse next tile
    }

    // ---- epilogue: Out = O / l ----
    const float inv0 = 1.f / l0s, inv1 = 1.f / l1s;
    float* out0 = Out + ((size_t)b * S_ + q0 + mr + gr) * D_;
    float* out1 = out0 + 8 * D_;
    #pragma unroll
    for (int nd = 0; nd < 16; ++nd) {
        int col = nd * 8 + t4 * 2;
        *(float2*)(out0 + col) = make_float2(o[nd][0] * inv0, o[nd][1] * inv0);
        *(float2*)(out1 + col) = make_float2(o[nd][2] * inv1, o[nd][3] * inv1);
    }
}

// ---------------------------------------------------------------------------
// Launch. Inputs (metadata order): query, key, value, scale_factor, dropout_p
// ---------------------------------------------------------------------------
extern "C" void kernel_launch(void* const* d_in, const int* in_sizes, int n_in,
                              void* d_out, int out_size)
{
    (void)in_sizes; (void)n_in; (void)out_size;
    const float* q  = (const float*)d_in[0];
    const float* k  = (const float*)d_in[1];
    const float* v  = (const float*)d_in[2];
    const float* sc = (const float*)d_in[3];
    float* out = (float*)d_out;

    cudaFuncSetAttribute(attn_kernel, cudaFuncAttributeMaxDynamicSharedMemorySize, SM_TOTAL);
    attn_kernel<<<dim3(S_ / BM, B_), 256, SM_TOTAL>>>(q, k, v, sc, out);
}

// round 3
// speedup vs baseline: 1.2641x; 1.2641x over previous
#include <cuda_runtime.h>
#include <cuda_bf16.h>
#include <cuda_fp16.h>
#include <cstdint>

// ---------------------------------------------------------------------------
// Problem constants: B=16, S=2048, D=128
// ---------------------------------------------------------------------------
#define B_  16
#define S_  2048
#define D_  128
#define BM  128          // q rows per CTA
#define BN  64           // kv cols per tile
#define NT  (S_ / BN)    // 32 tiles
#define SCP 68           // scale tile row stride (floats)

// SMEM layout (bytes)
#define SM_QHI 0                     // 128x128 bf16  (32 KB)
#define SM_QLO 32768                 // 32 KB
#define SM_KHI 65536                 // 64x128 bf16   (16 KB)
#define SM_KLO 81920                 // 16 KB
#define SM_V   98304                 // 64x128 fp16   (16 KB)
#define SM_SC  114688                // 128x68 fp32   (34816 B)
#define SM_EXM 149504                // 128x2 fp32 max exchange (1 KB)
#define SM_EXS 150528                // 128x2 fp32 sum exchange (1 KB)
#define SM_TOTAL 151552

// ---------------------------------------------------------------------------
// Helpers (plain sm_80-level PTX only — compiles for base sm_103 target)
// ---------------------------------------------------------------------------
__device__ __forceinline__ uint32_t smem_u32(const void* p) {
    uint32_t a;
    asm("{ .reg .u64 t; cvta.to.shared.u64 t, %1; cvt.u32.u64 %0, t; }" : "=r"(a) : "l"(p));
    return a;
}
__device__ __forceinline__ uint32_t sw128(uint32_t o) { return o ^ ((o >> 3) & 0x70); }

// SW128 blocked-atom K-major byte offset: atom = 8 rows x 64 bf16 (1024 B)
__device__ __forceinline__ uint32_t koff(int row, int col, int rdiv8) {
    uint32_t o = ((uint32_t)((row >> 3) + (col >> 6) * rdiv8) << 10)
               | ((uint32_t)(row & 7) << 7) | ((uint32_t)(col & 63) << 1);
    return sw128(o);
}

// bf16 hi/lo split of a pair, packed (a -> lo half, b -> hi half). 6 instrs.
__device__ __forceinline__ void split2(float a, float b, uint32_t& hi, uint32_t& lo) {
    asm("cvt.rn.bf16x2.f32 %0, %1, %2;" : "=r"(hi) : "f"(b), "f"(a));
    float fa = __uint_as_float(hi << 16);
    float fb = __uint_as_float(hi & 0xFFFF0000u);
    asm("cvt.rn.bf16x2.f32 %0, %1, %2;" : "=r"(lo) : "f"(b - fb), "f"(a - fa));
}

// pack two floats to f16x2 (a -> lo half)
__device__ __forceinline__ uint32_t pack_f16x2(float a, float b) {
    uint32_t r;
    asm("cvt.rn.f16x2.f32 %0, %1, %2;" : "=r"(r) : "f"(b), "f"(a));
    return r;
}

__device__ __forceinline__ float ex2f(float x) {
    float y; asm("ex2.approx.ftz.f32 %0, %1;" : "=f"(y) : "f"(x)); return y;
}

#define CP_ASYNC16(DST, SRC) \
    asm volatile("cp.async.cg.shared.global [%0], [%1], 16;" :: "r"(DST), "l"(SRC))
#define CP_COMMIT() asm volatile("cp.async.commit_group;" ::: "memory")
#define CP_WAIT0()  asm volatile("cp.async.wait_group 0;" ::: "memory")

#define LDSM4(R0, R1, R2, R3, ADDR) \
    asm volatile("ldmatrix.sync.aligned.m8n8.x4.shared.b16 {%0,%1,%2,%3}, [%4];" \
        : "=r"(R0), "=r"(R1), "=r"(R2), "=r"(R3) : "r"(ADDR))

#define LDSM4T(R0, R1, R2, R3, ADDR) \
    asm volatile("ldmatrix.sync.aligned.m8n8.x4.trans.shared.b16 {%0,%1,%2,%3}, [%4];" \
        : "=r"(R0), "=r"(R1), "=r"(R2), "=r"(R3) : "r"(ADDR))

#define MMABF16(D, A0, A1, A2, A3, B0, B1) \
    asm volatile("mma.sync.aligned.m16n8k16.row.col.f32.bf16.bf16.f32 " \
        "{%0,%1,%2,%3}, {%4,%5,%6,%7}, {%8,%9}, {%0,%1,%2,%3};" \
        : "+f"((D)[0]), "+f"((D)[1]), "+f"((D)[2]), "+f"((D)[3]) \
        : "r"(A0), "r"(A1), "r"(A2), "r"(A3), "r"(B0), "r"(B1))

#define MMAF16(D, A0, A1, A2, A3, B0, B1) \
    asm volatile("mma.sync.aligned.m16n8k16.row.col.f32.f16.f16.f32 " \
        "{%0,%1,%2,%3}, {%4,%5,%6,%7}, {%8,%9}, {%0,%1,%2,%3};" \
        : "+f"((D)[0]), "+f"((D)[1]), "+f"((D)[2]), "+f"((D)[3]) \
        : "r"(A0), "r"(A1), "r"(A2), "r"(A3), "r"(B0), "r"(B1))

// ---------------------------------------------------------------------------
// Flash attention: 1 CTA = (batch, 128 q rows), 16 warps.
// Warp w: row-group rg = w>>1 (16 q rows), kv-half h = w&1 (32 kv cols).
// QK^T: 3-term bf16 hi/lo split. PV: single-term fp16, O-partials per kv-half
// merged once at the end. log2(e) folded into Q at preload.
// ---------------------------------------------------------------------------
__global__ void __launch_bounds__(512, 1)
attn_kernel(const float* __restrict__ Q, const float* __restrict__ K,
            const float* __restrict__ V, const float* __restrict__ SC,
            float* __restrict__ Out)
{
    extern __shared__ char smem[];
    const uint32_t sb = smem_u32(smem);
    const int tid = threadIdx.x;
    const int wid = tid >> 5;
    const int lid = tid & 31;
    const int rg  = wid >> 1;       // q row-group (0..7)
    const int h   = wid & 1;        // kv-half
    const int gr  = lid >> 2;
    const int t4  = lid & 3;
    const int q0  = blockIdx.x * BM;
    const int b   = blockIdx.y;
    const float L2E = 1.4426950408889634f;

    const float* Qb = Q + ((size_t)b * S_ + q0) * D_;
    const float* Kb = K + (size_t)b * S_ * D_;
    const float* Vb = V + (size_t)b * S_ * D_;
    float* ssc = (float*)(smem + SM_SC);
    float* exm = (float*)(smem + SM_EXM);
    float* exs = (float*)(smem + SM_EXS);

    // ---- Q tile (hi/lo bf16, * log2e), once per CTA ----
    #pragma unroll
    for (int it = 0; it < 8; ++it) {
        int i = tid + it * 512;
        int row = i >> 5, c4 = i & 31;
        float4 v = *(const float4*)(Qb + row * D_ + c4 * 4);
        v.x *= L2E; v.y *= L2E; v.z *= L2E; v.w *= L2E;
        uint32_t h0, h1, l0, l1;
        split2(v.x, v.y, h0, l0); split2(v.z, v.w, h1, l1);
        uint32_t off = koff(row, c4 * 4, 16);
        *(uint2*)(smem + SM_QHI + off) = make_uint2(h0, h1);
        *(uint2*)(smem + SM_QLO + off) = make_uint2(l0, l1);
    }

    // O partial accumulator: 16 rows x 128 D cols (this warp's kv-half share)
    float o[16][4];
    #pragma unroll
    for (int nd = 0; nd < 16; ++nd) { o[nd][0] = o[nd][1] = o[nd][2] = o[nd][3] = 0.f; }
    float m0 = -INFINITY, m1 = -INFINITY, l0s = 0.f, l1s = 0.f;

    // lane constants (fragment addressing identical to the round-2 kernel)
    const int rowq  = rg * 16 + (lid & 7) + ((lid >> 3) & 1) * 8;
    const int colql = (lid >> 4) * 8;
    const int rk_b  = ((lid >> 4) << 3) + (lid & 7);
    const int colkl = ((lid >> 3) & 1) * 8;
    const int rv_b  = (((lid >> 3) & 1) << 3) + (lid & 7);
    const int cvl   = (lid >> 4) * 8;
    const int r0 = rg * 16 + gr, r1 = r0 + 8;

    for (int t = 0; t < NT; ++t) {
        const int kv0 = t * BN;

        // ---- scale tile via cp.async (raw copy; consumed after QK MMAs) ----
        #pragma unroll
        for (int it = 0; it < 4; ++it) {
            int i = tid + it * 512;
            int row = i >> 4, c4 = i & 15;
            const float* src = SC + (size_t)(q0 + row) * S_ + kv0 + c4 * 4;
            uint32_t dst = sb + SM_SC + (uint32_t)(row * SCP + c4 * 4) * 4;
            CP_ASYNC16(dst, src);
        }
        CP_COMMIT();

        // ---- K tile hi/lo bf16 ----
        #pragma unroll
        for (int it = 0; it < 4; ++it) {
            int i = tid + it * 512;
            int row = i >> 5, c4 = i & 31;
            float4 v = *(const float4*)(Kb + (size_t)(kv0 + row) * D_ + c4 * 4);
            uint32_t h0, h1, lo0, lo1;
            split2(v.x, v.y, h0, lo0); split2(v.z, v.w, h1, lo1);
            uint32_t off = koff(row, c4 * 4, 8);
            *(uint2*)(smem + SM_KHI + off) = make_uint2(h0, h1);
            *(uint2*)(smem + SM_KLO + off) = make_uint2(lo0, lo1);
        }
        // ---- V tile single fp16 ----
        #pragma unroll
        for (int it = 0; it < 4; ++it) {
            int i = tid + it * 512;
            int row = i >> 5, c4 = i & 31;
            float4 v = *(const float4*)(Vb + (size_t)(kv0 + row) * D_ + c4 * 4);
            uint32_t p0 = pack_f16x2(v.x, v.y);
            uint32_t p1 = pack_f16x2(v.z, v.w);
            uint32_t off = koff(row, c4 * 4, 8);
            *(uint2*)(smem + SM_V + off) = make_uint2(p0, p1);
        }
        __syncthreads();

        // ---- QK^T on this warp's kv-half: c[4][4] over 32 kv cols ----
        float c[4][4];
        #pragma unroll
        for (int nb = 0; nb < 4; ++nb) { c[nb][0] = c[nb][1] = c[nb][2] = c[nb][3] = 0.f; }
        #pragma unroll
        for (int ks = 0; ks < 8; ++ks) {
            const int cb = ks * 16;
            uint32_t qoff = koff(rowq, cb + colql, 16);
            uint32_t ah0, ah1, ah2, ah3, al0, al1, al2, al3;
            LDSM4(ah0, ah1, ah2, ah3, sb + SM_QHI + qoff);
            LDSM4(al0, al1, al2, al3, sb + SM_QLO + qoff);
            #pragma unroll
            for (int np2 = 0; np2 < 2; ++np2) {
                uint32_t kof = koff(h * 32 + np2 * 16 + rk_b, cb + colkl, 8);
                uint32_t bh0, bh1, bh2, bh3, bl0, bl1, bl2, bl3;
                LDSM4(bh0, bh1, bh2, bh3, sb + SM_KHI + kof);
                LDSM4(bl0, bl1, bl2, bl3, sb + SM_KLO + kof);
                // interleave the two accumulator chains for ILP
                MMABF16(c[2*np2],   ah0, ah1, ah2, ah3, bh0, bh1);
                MMABF16(c[2*np2+1], ah0, ah1, ah2, ah3, bh2, bh3);
                MMABF16(c[2*np2],   ah0, ah1, ah2, ah3, bl0, bl1);
                MMABF16(c[2*np2+1], ah0, ah1, ah2, ah3, bl2, bl3);
                MMABF16(c[2*np2],   al0, al1, al2, al3, bh0, bh1);
                MMABF16(c[2*np2+1], al0, al1, al2, al3, bh2, bh3);
            }
        }
        CP_WAIT0();
        __syncthreads();   // scale tile visible to all

        // ---- elementwise scale + partial row max over this kv-half ----
        float mt0 = -INFINITY, mt1 = -INFINITY;
        #pragma unroll
        for (int nb = 0; nb < 4; ++nb) {
            int col = h * 32 + nb * 8 + t4 * 2;
            float2 s0 = *(const float2*)(ssc + r0 * SCP + col);
            float2 s1 = *(const float2*)(ssc + r1 * SCP + col);
            c[nb][0] *= s0.x; c[nb][1] *= s0.y;
            c[nb][2] *= s1.x; c[nb][3] *= s1.y;
            mt0 = fmaxf(mt0, fmaxf(c[nb][0], c[nb][1]));
            mt1 = fmaxf(mt1, fmaxf(c[nb][2], c[nb][3]));
        }
        mt0 = fmaxf(mt0, __shfl_xor_sync(0xffffffffu, mt0, 1));
        mt0 = fmaxf(mt0, __shfl_xor_sync(0xffffffffu, mt0, 2));
        mt1 = fmaxf(mt1, __shfl_xor_sync(0xffffffffu, mt1, 1));
        mt1 = fmaxf(mt1, __shfl_xor_sync(0xffffffffu, mt1, 2));
        if (t4 == 0) { exm[r0 * 2 + h] = mt0; exm[r1 * 2 + h] = mt1; }
        __syncthreads();   // max exchange between warp pairs
        const float m0n = fmaxf(m0, fmaxf(exm[r0 * 2], exm[r0 * 2 + 1]));
        const float m1n = fmaxf(m1, fmaxf(exm[r1 * 2], exm[r1 * 2 + 1]));
        const float a0 = ex2f(m0 - m0n), a1 = ex2f(m1 - m1n);
        if (__any_sync(0xffffffffu, (a0 != 1.f) | (a1 != 1.f))) {
            #pragma unroll
            for (int nd = 0; nd < 16; ++nd) {
                o[nd][0] *= a0; o[nd][1] *= a0; o[nd][2] *= a1; o[nd][3] *= a1;
            }
        }
        float ls0 = 0.f, ls1 = 0.f;
        uint32_t pf[4][2];
        #pragma unroll
        for (int nb = 0; nb < 4; ++nb) {
            float p00 = ex2f(c[nb][0] - m0n), p01 = ex2f(c[nb][1] - m0n);
            float p10 = ex2f(c[nb][2] - m1n), p11 = ex2f(c[nb][3] - m1n);
            ls0 += p00 + p01; ls1 += p10 + p11;
            pf[nb][0] = pack_f16x2(p00, p01);
            pf[nb][1] = pack_f16x2(p10, p11);
        }
        ls0 += __shfl_xor_sync(0xffffffffu, ls0, 1);
        ls0 += __shfl_xor_sync(0xffffffffu, ls0, 2);
        ls1 += __shfl_xor_sync(0xffffffffu, ls1, 1);
        ls1 += __shfl_xor_sync(0xffffffffu, ls1, 2);
        if (t4 == 0) { exs[r0 * 2 + h] = ls0; exs[r1 * 2 + h] = ls1; }
        __syncthreads();   // sum exchange
        l0s = l0s * a0 + exs[r0 * 2] + exs[r0 * 2 + 1];
        l1s = l1s * a1 + exs[r1 * 2] + exs[r1 * 2 + 1];
        m0 = m0n; m1 = m1n;

        // ---- PV (single-term fp16): o_partial += P_half * V_half ----
        #pragma unroll
        for (int kk = 0; kk < 2; ++kk) {
            uint32_t pa0 = pf[2*kk][0],   pa1 = pf[2*kk][1];
            uint32_t pa2 = pf[2*kk+1][0], pa3 = pf[2*kk+1][1];
            const int rv = h * 32 + kk * 16 + rv_b;
            #pragma unroll
            for (int np2 = 0; np2 < 8; ++np2) {
                uint32_t voff = koff(rv, np2 * 16 + cvl, 8);
                uint32_t v0, v1, v2, v3;
                LDSM4T(v0, v1, v2, v3, sb + SM_V + voff);
                MMAF16(o[2*np2],   pa0, pa1, pa2, pa3, v0, v1);
                MMAF16(o[2*np2+1], pa0, pa1, pa2, pa3, v2, v3);
            }
        }
        __syncthreads();   // protect K/V/SC/ex smem for next tile
    }

    // ---- epilogue: merge kv-half partials through smem, store h==0 ----
    const float inv0 = 1.f / l0s, inv1 = 1.f / l1s;
    float* scratch = (float*)(smem + SM_KHI);  // 128 x 66 fp32 (33792 B)
    float* out0 = Out + ((size_t)b * S_ + q0 + r0) * D_;
    float* out1 = Out + ((size_t)b * S_ + q0 + r1) * D_;
    #pragma unroll
    for (int ch = 0; ch < 2; ++ch) {
        if (h == 1) {
            #pragma unroll
            for (int nd2 = 0; nd2 < 8; ++nd2) {
                int nd = ch * 8 + nd2;
                *(float2*)(scratch + r0 * 66 + nd2 * 8 + t4 * 2) = make_float2(o[nd][0], o[nd][1]);
                *(float2*)(scratch + r1 * 66 + nd2 * 8 + t4 * 2) = make_float2(o[nd][2], o[nd][3]);
            }
        }
        __syncthreads();
        if (h == 0) {
            #pragma unroll
            for (int nd2 = 0; nd2 < 8; ++nd2) {
                int nd = ch * 8 + nd2;
                float2 s0v = *(const float2*)(scratch + r0 * 66 + nd2 * 8 + t4 * 2);
                float2 s1v = *(const float2*)(scratch + r1 * 66 + nd2 * 8 + t4 * 2);
                *(float2*)(out0 + nd * 8 + t4 * 2) =
                    make_float2((o[nd][0] + s0v.x) * inv0, (o[nd][1] + s0v.y) * inv0);
                *(float2*)(out1 + nd * 8 + t4 * 2) =
                    make_float2((o[nd][2] + s1v.x) * inv1, (o[nd][3] + s1v.y) * inv1);
            }
        }
        __syncthreads();
    }
}

// ---------------------------------------------------------------------------
// Launch. Inputs (metadata order): query, key, value, scale_factor, dropout_p
// ---------------------------------------------------------------------------
extern "C" void kernel_launch(void* const* d_in, const int* in_sizes, int n_in,
                              void* d_out, int out_size)
{
    (void)in_sizes; (void)n_in; (void)out_size;
    const float* q  = (const float*)d_in[0];
    const float* k  = (const float*)d_in[1];
    const float* v  = (const float*)d_in[2];
    const float* sc = (const float*)d_in[3];
    float* out = (float*)d_out;

    cudaFuncSetAttribute(attn_kernel, cudaFuncAttributeMaxDynamicSharedMemorySize, SM_TOTAL);
    attn_kernel<<<dim3(S_ / BM, B_), 512, SM_TOTAL>>>(q, k, v, sc, out);
}

// round 6
// speedup vs baseline: 1.7045x; 1.3484x over previous
#include <cuda_runtime.h>
#include <cuda_bf16.h>
#include <cuda_fp16.h>
#include <cstdint>

// ---------------------------------------------------------------------------
// Problem constants: B=16, S=2048, D=128
// ---------------------------------------------------------------------------
#define B_  16
#define S_  2048
#define D_  128
#define BM  128          // q rows per CTA
#define BN  64           // kv cols per tile
#define NT  (S_ / BN)    // 32 tiles

// SMEM map (bytes):
//   [0, 32768)        Q hi  (128x128 bf16, SW128 blocked)
//   [32768, 65536)    Q lo
//   [65536, ...)      2 x BUFSZ staging buffers:
//       +0      K hi (16 KB)   +16384 K lo (16 KB)
//       +32768  V fp16 (16 KB) +49152 SC fp32 128x64 XOR-swizzled (32 KB)
#define SM_QHI 0
#define SM_QLO 32768
#define SM_BUF 65536
#define BUFSZ  81920
#define SM_TOTAL (SM_BUF + 2 * BUFSZ)   // 229376 B = 224 KB

// SC tile addressing: byte = row*256 + ((col*4) ^ ((row&7)<<5)).
// cp.async dst stays 16B aligned; reads are bank-conflict-free across rows.
#define SC_FIDX(row, col) ((row) * 64 + ((col) ^ (((row) & 7) << 3)))

// Pre-converted global scratch: per (batch, tile) 16 KB blobs in the exact
// pre-swizzle blocked-atom layout the smem tiles use.
#define BLOB (16384)
__device__ __align__(16) unsigned char g_khi[B_ * NT * BLOB];
__device__ __align__(16) unsigned char g_klo[B_ * NT * BLOB];
__device__ __align__(16) unsigned char g_vf [B_ * NT * BLOB];

// ---------------------------------------------------------------------------
// Helpers (plain sm_80-level PTX only)
// ---------------------------------------------------------------------------
__device__ __forceinline__ uint32_t smem_u32(const void* p) {
    uint32_t a;
    asm("{ .reg .u64 t; cvta.to.shared.u64 t, %1; cvt.u32.u64 %0, t; }" : "=r"(a) : "l"(p));
    return a;
}
__device__ __forceinline__ uint32_t sw128(uint32_t o) { return o ^ ((o >> 3) & 0x70); }

// blocked-atom raw offset (no swizzle): atom = 8 rows x 64 bf16 (1024 B)
__device__ __forceinline__ uint32_t koff_raw(int row, int col, int rdiv8) {
    return ((uint32_t)((row >> 3) + (col >> 6) * rdiv8) << 10)
         | ((uint32_t)(row & 7) << 7) | ((uint32_t)(col & 63) << 1);
}
__device__ __forceinline__ uint32_t koff(int row, int col, int rdiv8) {
    return sw128(koff_raw(row, col, rdiv8));
}

__device__ __forceinline__ void split2(float a, float b, uint32_t& hi, uint32_t& lo) {
    asm("cvt.rn.bf16x2.f32 %0, %1, %2;" : "=r"(hi) : "f"(b), "f"(a));
    float fa = __uint_as_float(hi << 16);
    float fb = __uint_as_float(hi & 0xFFFF0000u);
    asm("cvt.rn.bf16x2.f32 %0, %1, %2;" : "=r"(lo) : "f"(b - fb), "f"(a - fa));
}
__device__ __forceinline__ uint32_t pack_f16x2(float a, float b) {
    uint32_t r;
    asm("cvt.rn.f16x2.f32 %0, %1, %2;" : "=r"(r) : "f"(b), "f"(a));
    return r;
}
__device__ __forceinline__ float ex2f(float x) {
    float y; asm("ex2.approx.ftz.f32 %0, %1;" : "=f"(y) : "f"(x)); return y;
}

#define CP_ASYNC16(DST, SRC) \
    asm volatile("cp.async.cg.shared.global [%0], [%1], 16;" :: "r"(DST), "l"(SRC))
#define CP_COMMIT() asm volatile("cp.async.commit_group;" ::: "memory")
#define CP_WAIT1()  asm volatile("cp.async.wait_group 1;" ::: "memory")

#define LDSM4(R0, R1, R2, R3, ADDR) \
    asm volatile("ldmatrix.sync.aligned.m8n8.x4.shared.b16 {%0,%1,%2,%3}, [%4];" \
        : "=r"(R0), "=r"(R1), "=r"(R2), "=r"(R3) : "r"(ADDR))
#define LDSM4T(R0, R1, R2, R3, ADDR) \
    asm volatile("ldmatrix.sync.aligned.m8n8.x4.trans.shared.b16 {%0,%1,%2,%3}, [%4];" \
        : "=r"(R0), "=r"(R1), "=r"(R2), "=r"(R3) : "r"(ADDR))

#define MMABF16(D, A0, A1, A2, A3, B0, B1) \
    asm volatile("mma.sync.aligned.m16n8k16.row.col.f32.bf16.bf16.f32 " \
        "{%0,%1,%2,%3}, {%4,%5,%6,%7}, {%8,%9}, {%0,%1,%2,%3};" \
        : "+f"((D)[0]), "+f"((D)[1]), "+f"((D)[2]), "+f"((D)[3]) \
        : "r"(A0), "r"(A1), "r"(A2), "r"(A3), "r"(B0), "r"(B1))
#define MMAF16(D, A0, A1, A2, A3, B0, B1) \
    asm volatile("mma.sync.aligned.m16n8k16.row.col.f32.f16.f16.f32 " \
        "{%0,%1,%2,%3}, {%4,%5,%6,%7}, {%8,%9}, {%0,%1,%2,%3};" \
        : "+f"((D)[0]), "+f"((D)[1]), "+f"((D)[2]), "+f"((D)[3]) \
        : "r"(A0), "r"(A1), "r"(A2), "r"(A3), "r"(B0), "r"(B1))

// ---------------------------------------------------------------------------
// Pre-pass: convert K -> bf16 hi/lo blobs, V -> fp16 blob, blocked layout.
// Grid (NT, B), 256 threads.
// ---------------------------------------------------------------------------
__global__ void __launch_bounds__(256)
prepass_kernel(const float* __restrict__ K, const float* __restrict__ V)
{
    const int t = blockIdx.x, b = blockIdx.y;
    const float* Kt = K + ((size_t)b * S_ + t * BN) * D_;
    const float* Vt = V + ((size_t)b * S_ + t * BN) * D_;
    unsigned char* okh = g_khi + (size_t)(b * NT + t) * BLOB;
    unsigned char* okl = g_klo + (size_t)(b * NT + t) * BLOB;
    unsigned char* ov  = g_vf  + (size_t)(b * NT + t) * BLOB;

    #pragma unroll
    for (int it = 0; it < 8; ++it) {
        int i = threadIdx.x + it * 256;
        int row = i >> 5, c4 = i & 31;
        uint32_t off = koff_raw(row, c4 * 4, 8);
        float4 kv = *(const float4*)(Kt + (size_t)row * D_ + c4 * 4);
        uint32_t h0, h1, l0, l1;
        split2(kv.x, kv.y, h0, l0); split2(kv.z, kv.w, h1, l1);
        *(uint2*)(okh + off) = make_uint2(h0, h1);
        *(uint2*)(okl + off) = make_uint2(l0, l1);
        float4 vv = *(const float4*)(Vt + (size_t)row * D_ + c4 * 4);
        *(uint2*)(ov + off) = make_uint2(pack_f16x2(vv.x, vv.y), pack_f16x2(vv.z, vv.w));
    }
}

// ---------------------------------------------------------------------------
// Main flash-attention kernel. 1 CTA = (batch, 128 q rows), 16 warps:
// warp = (row-group rg = wid>>1, kv-half h = wid&1). Split-KV softmax:
// each half keeps private (m, l, O-partial); merged once in the epilogue.
// ---------------------------------------------------------------------------
__global__ void __launch_bounds__(512, 1)
attn_kernel(const float* __restrict__ Q, const float* __restrict__ SC,
            float* __restrict__ Out)
{
    extern __shared__ char smem[];
    const uint32_t sb = smem_u32(smem);
    const int tid = threadIdx.x;
    const int wid = tid >> 5;
    const int lid = tid & 31;
    const int rg  = wid >> 1;
    const int h   = wid & 1;
    const int gr  = lid >> 2;
    const int t4  = lid & 3;
    const int q0  = blockIdx.x * BM;
    const int b   = blockIdx.y;
    const float L2E = 1.4426950408889634f;

    const float* Qb = Q + ((size_t)b * S_ + q0) * D_;

    // ---- Q tile (hi/lo bf16, * log2e), once per CTA ----
    #pragma unroll
    for (int it = 0; it < 8; ++it) {
        int i = tid + it * 512;
        int row = i >> 5, c4 = i & 31;
        float4 v = *(const float4*)(Qb + row * D_ + c4 * 4);
        v.x *= L2E; v.y *= L2E; v.z *= L2E; v.w *= L2E;
        uint32_t h0, h1, l0, l1;
        split2(v.x, v.y, h0, l0); split2(v.z, v.w, h1, l1);
        uint32_t off = koff(row, c4 * 4, 16);
        *(uint2*)(smem + SM_QHI + off) = make_uint2(h0, h1);
        *(uint2*)(smem + SM_QLO + off) = make_uint2(l0, l1);
    }

    // ---- cp.async staging of one tile into buffer s ----
    const size_t bt_base = (size_t)(b * NT) * BLOB;
    auto issue_tile = [&](int t, int s) {
        const unsigned char* kh = g_khi + bt_base + (size_t)t * BLOB;
        const unsigned char* kl = g_klo + bt_base + (size_t)t * BLOB;
        const unsigned char* vv = g_vf  + bt_base + (size_t)t * BLOB;
        uint32_t db = sb + SM_BUF + (uint32_t)s * BUFSZ;
        #pragma unroll
        for (int j = tid; j < 1024; j += 512) {
            uint32_t sw = sw128((uint32_t)j * 16);
            CP_ASYNC16(db + sw,         kh + j * 16);
            CP_ASYNC16(db + 16384 + sw, kl + j * 16);
            CP_ASYNC16(db + 32768 + sw, vv + j * 16);
        }
        #pragma unroll
        for (int j = tid; j < 2048; j += 512) {
            int row = j >> 4, c4 = j & 15;
            const float* src = SC + (size_t)(q0 + row) * S_ + t * BN + c4 * 4;
            uint32_t dst = db + 49152
                         + (uint32_t)(row * 256 + ((c4 * 16) ^ ((row & 7) << 5)));
            CP_ASYNC16(dst, src);
        }
    };

    issue_tile(0, 0); CP_COMMIT();
    issue_tile(1, 1); CP_COMMIT();

    // O partial accumulator: 16 rows x 128 D cols (this warp's kv-half share)
    float o[16][4];
    #pragma unroll
    for (int nd = 0; nd < 16; ++nd) { o[nd][0] = o[nd][1] = o[nd][2] = o[nd][3] = 0.f; }
    float m0 = -INFINITY, m1 = -INFINITY, l0s = 0.f, l1s = 0.f;

    // lane constants
    const int rowq  = rg * 16 + (lid & 7) + ((lid >> 3) & 1) * 8;
    const int colql = (lid >> 4) * 8;
    const int rk_b  = ((lid >> 4) << 3) + (lid & 7);
    const int colkl = ((lid >> 3) & 1) * 8;
    const int rv_b  = (((lid >> 3) & 1) << 3) + (lid & 7);
    const int cvl   = (lid >> 4) * 8;
    const int r0 = rg * 16 + gr, r1 = r0 + 8;

    for (int t = 0; t < NT; ++t) {
        CP_WAIT1();
        __syncthreads();
        const uint32_t kb = sb + SM_BUF + (uint32_t)(t & 1) * BUFSZ;
        const float* ssc = (const float*)(smem + SM_BUF + (t & 1) * BUFSZ + 49152);

        // ---- QK^T on this warp's kv-half (3-term bf16 hi/lo) ----
        float c[4][4];
        #pragma unroll
        for (int nb = 0; nb < 4; ++nb) { c[nb][0] = c[nb][1] = c[nb][2] = c[nb][3] = 0.f; }
        #pragma unroll
        for (int ks = 0; ks < 8; ++ks) {
            const int cb = ks * 16;
            uint32_t qoff = koff(rowq, cb + colql, 16);
            uint32_t ah0, ah1, ah2, ah3, al0, al1, al2, al3;
            LDSM4(ah0, ah1, ah2, ah3, sb + SM_QHI + qoff);
            LDSM4(al0, al1, al2, al3, sb + SM_QLO + qoff);
            #pragma unroll
            for (int np2 = 0; np2 < 2; ++np2) {
                uint32_t kof = koff(h * 32 + np2 * 16 + rk_b, cb + colkl, 8);
                uint32_t bh0, bh1, bh2, bh3, bl0, bl1, bl2, bl3;
                LDSM4(bh0, bh1, bh2, bh3, kb + kof);
                LDSM4(bl0, bl1, bl2, bl3, kb + 16384 + kof);
                MMABF16(c[2*np2],   ah0, ah1, ah2, ah3, bh0, bh1);
                MMABF16(c[2*np2+1], ah0, ah1, ah2, ah3, bh2, bh3);
                MMABF16(c[2*np2],   ah0, ah1, ah2, ah3, bl0, bl1);
                MMABF16(c[2*np2+1], ah0, ah1, ah2, ah3, bl2, bl3);
                MMABF16(c[2*np2],   al0, al1, al2, al3, bh0, bh1);
                MMABF16(c[2*np2+1], al0, al1, al2, al3, bh2, bh3);
            }
        }

        // ---- elementwise scale + warp-local online softmax (split-KV) ----
        float mt0 = -INFINITY, mt1 = -INFINITY;
        #pragma unroll
        for (int nb = 0; nb < 4; ++nb) {
            int col = h * 32 + nb * 8 + t4 * 2;
            float2 s0 = *(const float2*)(ssc + SC_FIDX(r0, col));
            float2 s1 = *(const float2*)(ssc + SC_FIDX(r1, col));
            c[nb][0] *= s0.x; c[nb][1] *= s0.y;
            c[nb][2] *= s1.x; c[nb][3] *= s1.y;
            mt0 = fmaxf(mt0, fmaxf(c[nb][0], c[nb][1]));
            mt1 = fmaxf(mt1, fmaxf(c[nb][2], c[nb][3]));
        }
        mt0 = fmaxf(mt0, __shfl_xor_sync(0xffffffffu, mt0, 1));
        mt0 = fmaxf(mt0, __shfl_xor_sync(0xffffffffu, mt0, 2));
        mt1 = fmaxf(mt1, __shfl_xor_sync(0xffffffffu, mt1, 1));
        mt1 = fmaxf(mt1, __shfl_xor_sync(0xffffffffu, mt1, 2));
        const float m0n = fmaxf(m0, mt0), m1n = fmaxf(m1, mt1);
        const float a0 = ex2f(m0 - m0n), a1 = ex2f(m1 - m1n);
        if (__any_sync(0xffffffffu, (a0 != 1.f) | (a1 != 1.f))) {
            #pragma unroll
            for (int nd = 0; nd < 16; ++nd) {
                o[nd][0] *= a0; o[nd][1] *= a0; o[nd][2] *= a1; o[nd][3] *= a1;
            }
        }
        float ls0 = 0.f, ls1 = 0.f;
        uint32_t pf[4][2];
        #pragma unroll
        for (int nb = 0; nb < 4; ++nb) {
            float p00 = ex2f(c[nb][0] - m0n), p01 = ex2f(c[nb][1] - m0n);
            float p10 = ex2f(c[nb][2] - m1n), p11 = ex2f(c[nb][3] - m1n);
            ls0 += p00 + p01; ls1 += p10 + p11;
            pf[nb][0] = pack_f16x2(p00, p01);
            pf[nb][1] = pack_f16x2(p10, p11);
        }
        ls0 += __shfl_xor_sync(0xffffffffu, ls0, 1);
        ls0 += __shfl_xor_sync(0xffffffffu, ls0, 2);
        ls1 += __shfl_xor_sync(0xffffffffu, ls1, 1);
        ls1 += __shfl_xor_sync(0xffffffffu, ls1, 2);
        l0s = l0s * a0 + ls0; l1s = l1s * a1 + ls1;
        m0 = m0n; m1 = m1n;

        // ---- PV (single-term fp16): o_partial += P_half * V_half ----
        #pragma unroll
        for (int kk = 0; kk < 2; ++kk) {
            uint32_t pa0 = pf[2*kk][0],   pa1 = pf[2*kk][1];
            uint32_t pa2 = pf[2*kk+1][0], pa3 = pf[2*kk+1][1];
            const int rv = h * 32 + kk * 16 + rv_b;
            #pragma unroll
            for (int np2 = 0; np2 < 8; ++np2) {
                uint32_t voff = koff(rv, np2 * 16 + cvl, 8);
                uint32_t v0, v1, v2, v3;
                LDSM4T(v0, v1, v2, v3, kb + 32768 + voff);
                MMAF16(o[2*np2],   pa0, pa1, pa2, pa3, v0, v1);
                MMAF16(o[2*np2+1], pa0, pa1, pa2, pa3, v2, v3);
            }
        }
        __syncthreads();     // all warps done with buf (t&1) before overwrite
        if (t + 2 < NT) issue_tile(t + 2, t & 1);
        CP_COMMIT();         // commit (possibly empty) to keep group indexing
    }

    // ---- epilogue: split-KV merge of the two kv-half partials ----
    // Per warp: beta0 applies to its r0 rows (o[nd][0..1]),
    //           beta1 applies to its r1 rows (o[nd][2..3]).   [R5 bugfix]
    float* exm = (float*)(smem + SM_BUF);          // buffers are dead now
    float* exl = (float*)(smem + SM_BUF + 1024);
    float* oscr = (float*)(smem + SM_BUF + 4096);  // 128 x 66 fp32
    if (t4 == 0) {
        exm[r0 * 2 + h] = m0; exm[r1 * 2 + h] = m1;
        exl[r0 * 2 + h] = l0s; exl[r1 * 2 + h] = l1s;
    }
    __syncthreads();
    float mA0 = exm[r0 * 2], mB0 = exm[r0 * 2 + 1];
    float mf0 = fmaxf(mA0, mB0);
    float lf0 = exl[r0 * 2] * ex2f(mA0 - mf0) + exl[r0 * 2 + 1] * ex2f(mB0 - mf0);
    float beta0 = ex2f(m0 - mf0) / lf0;
    float mA1 = exm[r1 * 2], mB1 = exm[r1 * 2 + 1];
    float mf1 = fmaxf(mA1, mB1);
    float lf1 = exl[r1 * 2] * ex2f(mA1 - mf1) + exl[r1 * 2 + 1] * ex2f(mB1 - mf1);
    float beta1 = ex2f(m1 - mf1) / lf1;

    float* out0 = Out + ((size_t)b * S_ + q0 + r0) * D_;
    float* out1 = Out + ((size_t)b * S_ + q0 + r1) * D_;
    #pragma unroll
    for (int ch = 0; ch < 2; ++ch) {
        if (h == 1) {
            #pragma unroll
            for (int nd2 = 0; nd2 < 8; ++nd2) {
                int nd = ch * 8 + nd2;
                *(float2*)(oscr + r0 * 66 + nd2 * 8 + t4 * 2) =
                    make_float2(o[nd][0] * beta0, o[nd][1] * beta0);
                *(float2*)(oscr + r1 * 66 + nd2 * 8 + t4 * 2) =
                    make_float2(o[nd][2] * beta1, o[nd][3] * beta1);
            }
        }
        __syncthreads();
        if (h == 0) {
            #pragma unroll
            for (int nd2 = 0; nd2 < 8; ++nd2) {
                int nd = ch * 8 + nd2;
                float2 s0v = *(const float2*)(oscr + r0 * 66 + nd2 * 8 + t4 * 2);
                float2 s1v = *(const float2*)(oscr + r1 * 66 + nd2 * 8 + t4 * 2);
                *(float2*)(out0 + nd * 8 + t4 * 2) =
                    make_float2(o[nd][0] * beta0 + s0v.x, o[nd][1] * beta0 + s0v.y);
                *(float2*)(out1 + nd * 8 + t4 * 2) =
                    make_float2(o[nd][2] * beta1 + s1v.x, o[nd][3] * beta1 + s1v.y);
            }
        }
        __syncthreads();
    }
}

// ---------------------------------------------------------------------------
// Launch. Inputs (metadata order): query, key, value, scale_factor, dropout_p
// ---------------------------------------------------------------------------
extern "C" void kernel_launch(void* const* d_in, const int* in_sizes, int n_in,
                              void* d_out, int out_size)
{
    (void)in_sizes; (void)n_in; (void)out_size;
    const float* q  = (const float*)d_in[0];
    const float* k  = (const float*)d_in[1];
    const float* v  = (const float*)d_in[2];
    const float* sc = (const float*)d_in[3];
    float* out = (float*)d_out;

    prepass_kernel<<<dim3(NT, B_), 256>>>(k, v);

    cudaFuncSetAttribute(attn_kernel, cudaFuncAttributeMaxDynamicSharedMemorySize, SM_TOTAL);
    attn_kernel<<<dim3(S_ / BM, B_), 512, SM_TOTAL>>>(q, sc, out);
}